// round 15
// baseline (speedup 1.0000x reference)
#include <cuda_runtime.h>
#include <cstdint>

#define BS   4
#define NVW  12
#define CIN  384
#define COUT 32
#define HW   4096
#define NIMG (BS * NVW)
#define NVOX (64 * 64 * 64)

// Scratch: reduced features in (img, pixel, channel) layout -> 25.2 MB.
__device__ float g_red[(size_t)NIMG * HW * COUT];

// ---------------------------------------------------------------------------
// Kernel A: channel reduce 384 -> 32. Channel-pair f32x2 accumulators (R11)
// + v3: double-buffered global prefetch so each warp always has the next
// 8-channel batch in flight while computing the current one.
// ---------------------------------------------------------------------------
__global__ __launch_bounds__(256, 2) void reduce_kernel(
    const float* __restrict__ vit, const float* __restrict__ wr,
    const float* __restrict__ br)
{
    extern __shared__ float ws[];  // [CIN][COUT] floats, 48 KB
    const int img = blockIdx.y;

    for (int i = threadIdx.x; i < CIN * COUT; i += 256) {
        const int c = i >> 5, o = i & 31;
        ws[i] = wr[o * CIN + c];
    }
    __syncthreads();

    const int pix0 = (blockIdx.x * 256 + threadIdx.x) * 2;
    const float* in = vit + (size_t)img * CIN * HW + pix0;

    unsigned long long acc0[16], acc1[16];
#pragma unroll
    for (int j = 0; j < 16; j++) { acc0[j] = 0ull; acc1[j] = 0ull; }

    auto compute8 = [&](const float2* xr, int cbase) {
#pragma unroll
        for (int u = 0; u < 8; u++) {
            unsigned long long xa, xb;
            asm("mov.b64 %0, {%1, %1};" : "=l"(xa) : "f"(xr[u].x));
            asm("mov.b64 %0, {%1, %1};" : "=l"(xb) : "f"(xr[u].y));
            const ulonglong2* wrow =
                reinterpret_cast<const ulonglong2*>(ws + (cbase + u) * COUT);
#pragma unroll
            for (int o4 = 0; o4 < 8; o4++) {
                const ulonglong2 wv = wrow[o4];  // LDS.128: 4 distinct weights
                asm("fma.rn.f32x2 %0, %1, %2, %0;" : "+l"(acc0[2*o4])   : "l"(wv.x), "l"(xa));
                asm("fma.rn.f32x2 %0, %1, %2, %0;" : "+l"(acc0[2*o4+1]) : "l"(wv.y), "l"(xa));
                asm("fma.rn.f32x2 %0, %1, %2, %0;" : "+l"(acc1[2*o4])   : "l"(wv.x), "l"(xb));
                asm("fma.rn.f32x2 %0, %1, %2, %0;" : "+l"(acc1[2*o4+1]) : "l"(wv.y), "l"(xb));
            }
        }
    };

    float2 xa[8], xb[8];
#pragma unroll
    for (int u = 0; u < 8; u++)
        xa[u] = *reinterpret_cast<const float2*>(in + (size_t)u * HW);

    for (int c0 = 0; c0 < CIN; c0 += 16) {
#pragma unroll
        for (int u = 0; u < 8; u++)      // prefetch second half of this pair
            xb[u] = *reinterpret_cast<const float2*>(in + (size_t)(c0 + 8 + u) * HW);
        compute8(xa, c0);
        if (c0 + 16 < CIN) {
#pragma unroll
            for (int u = 0; u < 8; u++)  // prefetch next pair's first half
                xa[u] = *reinterpret_cast<const float2*>(in + (size_t)(c0 + 16 + u) * HW);
        }
        compute8(xb, c0 + 8);
    }

    float v0[COUT], v1[COUT];
#pragma unroll
    for (int j = 0; j < 16; j++) {
        float a, bq, c, d;
        asm("mov.b64 {%0, %1}, %2;" : "=f"(a), "=f"(bq) : "l"(acc0[j]));
        asm("mov.b64 {%0, %1}, %2;" : "=f"(c), "=f"(d)  : "l"(acc1[j]));
        const float b0 = __ldg(br + 2*j), b1 = __ldg(br + 2*j + 1);
        v0[2*j] = a + b0; v0[2*j+1] = bq + b1;
        v1[2*j] = c + b0; v1[2*j+1] = d + b1;
    }
    float4* out0 = reinterpret_cast<float4*>(
        g_red + ((size_t)img * HW + pix0) * COUT);
#pragma unroll
    for (int k = 0; k < 8; k++)
        out0[k] = make_float4(v0[4*k], v0[4*k+1], v0[4*k+2], v0[4*k+3]);
    float4* out1 = out0 + 8;
#pragma unroll
    for (int k = 0; k < 8; k++)
        out1[k] = make_float4(v1[4*k], v1[4*k+1], v1[4*k+2], v1[4*k+3]);
}

// ---------------------------------------------------------------------------
// Kernel B v3: warp-uniform, branch-free backprojection.
//   lane = channel (32 lanes x 4B = ONE 128B line per (z,view) -> 1 wavefront
//   per LDG, no divergence). Warp owns (col, 16 z); CTA = 2 cols x 64 z.
//   Invalid views: offset 0 + mask 0.0, folded via fmaf. 16 independent
//   LDG.32 per view -> high MLP, zero BSSY/BSYNC.
//   Output staged through padded smem transpose for coalesced stores.
// ---------------------------------------------------------------------------
__global__ __launch_bounds__(256) void backproj_kernel(
    const float* __restrict__ proj, float* __restrict__ out)
{
    __shared__ float P[NVW][12];
    __shared__ unsigned int offt[2 * NVW * 64];  // byte offsets (0 if invalid)
    __shared__ float maskt[2 * NVW * 64];        // 1.0 / 0.0
    __shared__ float trans[128][33];             // padded transpose buffer

    const int b   = blockIdx.y;
    const int tid = threadIdx.x;

    if (tid < NVW * 12) {
        const int v = tid / 12, k = tid % 12;
        float val = proj[((size_t)b * NVW + v) * 12 + k];
        if (k < 8) val *= 0.25f;  // rows 0,1 divided by STRIDE=4
        P[v][k] = val;
    }
    __syncthreads();

    // ---- Phase 1: pixel tables (1536 entries, 6 per thread) ----
#pragma unroll
    for (int k = 0; k < 6; k++) {
        const int e   = tid + k * 256;
        const int zi  = e & 63;
        const int t2  = e >> 6;
        const int v   = t2 % NVW;
        const int col = t2 / NVW;               // 0 or 1
        const int cg  = blockIdx.x * 2 + col;   // global column
        const float wx = (cg >> 6) * 0.04f - 1.28f;
        const float wy = (cg & 63) * 0.04f - 1.28f;
        const float wz = zi * 0.04f - 1.28f;

        const float c0 = P[v][0]*wx + P[v][1]*wy + P[v][2]*wz  + P[v][3];
        const float c1 = P[v][4]*wx + P[v][5]*wy + P[v][6]*wz  + P[v][7];
        const float c2 = P[v][8]*wx + P[v][9]*wy + P[v][10]*wz + P[v][11];

        unsigned int off = 0u;
        float m = 0.f;
        if (c2 > 0.f) {
            const int px = __float2int_rn(c0 / c2);  // round-half-even, IEEE div
            const int py = __float2int_rn(c1 / c2);
            if (((unsigned)px < 64u) && ((unsigned)py < 64u)) {
                off = (unsigned int)(((py << 6) + px) << 7);  // *128 bytes
                m = 1.f;
            }
        }
        offt[e]  = off;
        maskt[e] = m;
    }
    __syncthreads();

    // ---- Phase 2: gather + accumulate (warp-uniform control) ----
    const int warp = tid >> 5, lane = tid & 31;
    const int col  = warp >> 2;        // 0..1
    const int zr   = (warp & 3) << 4;  // 0,16,32,48

    float acc[16], cnt[16];
#pragma unroll
    for (int z = 0; z < 16; z++) { acc[z] = 0.f; cnt[z] = 0.f; }

    const char* bb = reinterpret_cast<const char*>(g_red)
                   + (size_t)b * NVW * HW * COUT * sizeof(float)
                   + lane * sizeof(float);

    for (int v = 0; v < NVW; v++) {
        const char* fb = bb + (size_t)v * HW * COUT * sizeof(float);
        const int tbase = (col * NVW + v) * 64 + zr;
#pragma unroll
        for (int g = 0; g < 4; g++) {
            const uint4  o4 = *reinterpret_cast<const uint4*>(&offt[tbase + g*4]);
            const float4 m4 = *reinterpret_cast<const float4*>(&maskt[tbase + g*4]);
            const float t0 = *reinterpret_cast<const float*>(fb + o4.x);
            const float t1 = *reinterpret_cast<const float*>(fb + o4.y);
            const float t2 = *reinterpret_cast<const float*>(fb + o4.z);
            const float t3 = *reinterpret_cast<const float*>(fb + o4.w);
            acc[g*4+0] = fmaf(t0, m4.x, acc[g*4+0]); cnt[g*4+0] += m4.x;
            acc[g*4+1] = fmaf(t1, m4.y, acc[g*4+1]); cnt[g*4+1] += m4.y;
            acc[g*4+2] = fmaf(t2, m4.z, acc[g*4+2]); cnt[g*4+2] += m4.z;
            acc[g*4+3] = fmaf(t3, m4.w, acc[g*4+3]); cnt[g*4+3] += m4.w;
        }
    }

    // ---- Normalize + smem transpose ----
#pragma unroll
    for (int zz = 0; zz < 16; zz++) {
        const float c_ = cnt[zz];
        const float iv = (c_ > 0.f) ? (1.f / c_) : 0.f;
        trans[col * 64 + zr + zz][lane] = acc[zz] * iv;
    }
    __syncthreads();

    // ---- Coalesced store: 32 chan x 128 consecutive voxels ----
    float* ob = out + (size_t)b * COUT * NVOX + (size_t)blockIdx.x * 128;
#pragma unroll
    for (int k = 0; k < 16; k++) {
        const int idx = tid + k * 256;
        const int c = idx >> 7;      // channel
        const int n = idx & 127;     // voxel within CTA block
        ob[(size_t)c * NVOX + n] = trans[n][c];
    }
}

// ---------------------------------------------------------------------------
extern "C" void kernel_launch(void* const* d_in, const int* in_sizes, int n_in,
                              void* d_out, int out_size)
{
    const float* vit = (const float*)d_in[0];  // (4,12,384,64,64)
    const float* wr  = (const float*)d_in[1];  // (32,384)
    const float* br  = (const float*)d_in[2];  // (32,)
    const float* pj  = (const float*)d_in[3];  // (4,12,3,4)
    float* out = (float*)d_out;                // (4,32,64,64,64)

    const int smemA = CIN * COUT * 4;  // 48 KB un-duplicated weights
    cudaFuncSetAttribute(reduce_kernel,
                         cudaFuncAttributeMaxDynamicSharedMemorySize, smemA);

    dim3 gA(8, NIMG);              // 8 blocks * 256 thr * 2 pix = 4096 pixels
    reduce_kernel<<<gA, 256, smemA>>>(vit, wr, br);

    dim3 gB(2048, BS);             // 2048 CTAs * 2 cols * 64 z = 262144 voxels
    backproj_kernel<<<gB, 256>>>(pj, out);
}